// round 1
// baseline (speedup 1.0000x reference)
#include <cuda_runtime.h>
#include <cstdint>
#include <cstddef>

#define B_   32
#define DIN  64
#define DS   1024
#define L_   2048

// 268 MB scratch for u_proj in [B][L][DS] layout (coalesced reads in phase 2)
__device__ float g_uproj[(size_t)B_ * L_ * DS];

__device__ __forceinline__ uint32_t f2tf32(float f) {
    uint32_t r;
    asm("cvt.rna.tf32.f32 %0, %1;" : "=r"(r) : "f"(f));
    return r;
}

// ---------------------------------------------------------------------------
// Phase 1: GEMM  uproj[b][l][p] = sum_h u[b][h][l] * w_in[p][h]
// Block tile: BM=64 (l) x BN=64 (p), K=64 fully resident in smem.
// 4 warps in 2x2 grid, warp tile 32x32 = 2(m16) x 4(n8) mma.m16n8k8 tiles.
// ---------------------------------------------------------------------------
#define BM 64
#define BN 64
#define SA 72   // smem stride pad: banks (8t+g) conflict-free for frag loads
#define SB 72

__global__ __launch_bounds__(128)
void gemm_kernel(const float* __restrict__ u,
                 const float* __restrict__ w_in) {
    __shared__ uint32_t As[DIN * SA];  // As[k][m]  (m = local l)
    __shared__ uint32_t Bs[DIN * SB];  // Bs[k][n]  (n = local p)

    const int l0  = blockIdx.x * BM;
    const int p0  = blockIdx.y * BN;
    const int b   = blockIdx.z;
    const int tid = threadIdx.x;

    // Load A tile: u[b][h][l0..l0+63], 64x64 floats = 1024 float4 (8/thread)
    const float* ub = u + (size_t)b * DIN * L_;
    #pragma unroll
    for (int it = 0; it < 8; it++) {
        int s = tid + it * 128;       // 0..1023
        int h = s >> 4;
        int c = s & 15;               // float4 index along l
        float4 v = *(const float4*)(ub + (size_t)h * L_ + l0 + 4 * c);
        uint32_t* dst = &As[h * SA + 4 * c];
        dst[0] = f2tf32(v.x); dst[1] = f2tf32(v.y);
        dst[2] = f2tf32(v.z); dst[3] = f2tf32(v.w);
    }
    // Load B tile: w_in[p0+n][k] transposed into Bs[k][n]
    #pragma unroll
    for (int it = 0; it < 8; it++) {
        int s = tid + it * 128;
        int n = s >> 4;
        int c = s & 15;               // float4 index along k
        float4 v = *(const float4*)(w_in + (size_t)(p0 + n) * DIN + 4 * c);
        Bs[(4 * c + 0) * SB + n] = f2tf32(v.x);
        Bs[(4 * c + 1) * SB + n] = f2tf32(v.y);
        Bs[(4 * c + 2) * SB + n] = f2tf32(v.z);
        Bs[(4 * c + 3) * SB + n] = f2tf32(v.w);
    }
    __syncthreads();

    const int warp = tid >> 5, lane = tid & 31;
    const int wm = warp >> 1, wn = warp & 1;
    const int g = lane >> 2, t = lane & 3;

    float acc[2][4][4];
    #pragma unroll
    for (int im = 0; im < 2; im++)
        #pragma unroll
        for (int in = 0; in < 4; in++)
            #pragma unroll
            for (int q = 0; q < 4; q++) acc[im][in][q] = 0.f;

    #pragma unroll
    for (int ks = 0; ks < 8; ks++) {
        const int kk = ks * 8;
        uint32_t a[2][4], bf[4][2];
        #pragma unroll
        for (int im = 0; im < 2; im++) {
            int r = wm * 32 + im * 16 + g;
            a[im][0] = As[(kk + t) * SA + r];          // (row g,   col t)
            a[im][1] = As[(kk + t) * SA + r + 8];      // (row g+8, col t)
            a[im][2] = As[(kk + t + 4) * SA + r];      // (row g,   col t+4)
            a[im][3] = As[(kk + t + 4) * SA + r + 8];  // (row g+8, col t+4)
        }
        #pragma unroll
        for (int in = 0; in < 4; in++) {
            int n = wn * 32 + in * 8 + g;
            bf[in][0] = Bs[(kk + t) * SB + n];         // (k t,   n g)
            bf[in][1] = Bs[(kk + t + 4) * SB + n];     // (k t+4, n g)
        }
        #pragma unroll
        for (int im = 0; im < 2; im++)
            #pragma unroll
            for (int in = 0; in < 4; in++) {
                asm volatile(
                    "mma.sync.aligned.m16n8k8.row.col.f32.tf32.tf32.f32 "
                    "{%0,%1,%2,%3}, {%4,%5,%6,%7}, {%8,%9}, {%0,%1,%2,%3};"
                    : "+f"(acc[im][in][0]), "+f"(acc[im][in][1]),
                      "+f"(acc[im][in][2]), "+f"(acc[im][in][3])
                    : "r"(a[im][0]), "r"(a[im][1]), "r"(a[im][2]), "r"(a[im][3]),
                      "r"(bf[in][0]), "r"(bf[in][1]));
            }
    }

    // Epilogue: uproj[b][l0+row][p0+col], float2 stores
    float* outp = g_uproj + ((size_t)b * L_ + l0) * DS + p0;
    #pragma unroll
    for (int im = 0; im < 2; im++) {
        int r0 = wm * 32 + im * 16 + g;
        #pragma unroll
        for (int in = 0; in < 4; in++) {
            int c0 = wn * 32 + in * 8 + t * 2;
            *(float2*)(outp + (size_t)r0 * DS + c0) =
                make_float2(acc[im][in][0], acc[im][in][1]);
            *(float2*)(outp + (size_t)(r0 + 8) * DS + c0) =
                make_float2(acc[im][in][2], acc[im][in][3]);
        }
    }
}

// ---------------------------------------------------------------------------
// Phase 2: per-(b,p) recurrence, chunked over time with smem transpose so
// output writes to [B][DS][L] are coalesced (32 consecutive l per warp-row).
//   pre = up + x*d + bias;  x = 0.5*x + 0.5*tanh(pre)
//   tanh(pre) = 1 - 2/(e^{2*pre}+1);  z = 2*log2e*(pre) folded into fma consts
// ---------------------------------------------------------------------------
#define PP 128
#define TC 32

__global__ __launch_bounds__(PP)
void recur_kernel(const float* __restrict__ w_hh,
                  const float* __restrict__ bias,
                  float* __restrict__ out) {
    __shared__ float buf[TC][PP + 1];

    const int tid = threadIdx.x;
    const int p0  = blockIdx.x * PP;
    const int p   = p0 + tid;
    const int b   = blockIdx.y;

    const float C2L = 2.8853900817779268f;  // 2*log2(e)
    const float d   = w_hh[(size_t)p * DS + p];     // diagonal element
    const float dp  = d * C2L;
    const float bz  = bias[p] * C2L;

    const float* up = g_uproj + (size_t)b * L_ * DS + p;
    float* ob = out + (size_t)b * DS * L_;

    const int wt = tid & 31;   // lane -> time index within chunk
    const int wr = tid >> 5;   // warp -> base p-row for output stage

    float x = 0.f;
    for (int l = 0; l < L_; l += TC) {
        // Batched loads (MLP=32), fold bias+2log2e off the critical path
        float upb[TC];
        #pragma unroll
        for (int t = 0; t < TC; t++)
            upb[t] = fmaf(up[(size_t)(l + t) * DS], C2L, bz);

        // Serial chain: fma -> ex2 -> add -> rcp -> sub  (~44 cyc/step)
        #pragma unroll
        for (int t = 0; t < TC; t++) {
            float z = fmaf(x, dp, upb[t]);       // 2*log2e*pre
            float e;
            asm("ex2.approx.f32 %0, %1;" : "=f"(e) : "f"(z));  // e^{2*pre}
            float h = fmaf(0.5f, x, 0.5f);       // off critical path
            float den = e + 1.0f;
            float r;
            asm("rcp.approx.f32 %0, %1;" : "=f"(r) : "f"(den));
            x = h - r;                            // 0.5x + 0.5 - 1/(e+1)
            buf[t][tid] = x;
        }
        __syncthreads();

        // Transposed write: each warp writes 32 consecutive l for one p-row
        #pragma unroll
        for (int j = 0; j < TC; j++) {
            int pr = wr + j * 4;                  // covers 0..127
            ob[(size_t)(p0 + pr) * L_ + l + wt] = buf[wt][pr];
        }
        __syncthreads();
    }
}

extern "C" void kernel_launch(void* const* d_in, const int* in_sizes, int n_in,
                              void* d_out, int out_size) {
    const float* u    = (const float*)d_in[0];  // [32, 64, 2048]
    const float* w_in = (const float*)d_in[1];  // [1024, 64]
    const float* w_hh = (const float*)d_in[2];  // [1024, 1024]
    const float* bias = (const float*)d_in[3];  // [1024]
    float* out = (float*)d_out;                 // [32, 1024, 2048] fp32

    dim3 g1(L_ / BM, DS / BN, B_);   // 32 x 16 x 32 blocks
    gemm_kernel<<<g1, 128>>>(u, w_in);

    dim3 g2(DS / PP, B_);            // 8 x 32 = 256 blocks
    recur_kernel<<<g2, PP>>>(w_hh, bias, out);
}

// round 2
// speedup vs baseline: 1.9691x; 1.9691x over previous
#include <cuda_runtime.h>
#include <cstdint>
#include <cstddef>

#define B_   32
#define DIN  64
#define DS   1024
#define L_   2048
#define PP   128      // p per block
#define TC   32       // timesteps per chunk
#define RS   (PP + 1) // smem row stride (floats), odd -> conflict-free transpose

__device__ __forceinline__ uint32_t f2tf32(float f) {
    uint32_t r;
    asm("cvt.rna.tf32.f32 %0, %1;" : "=r"(r) : "f"(f));
    return r;
}

#define BAR_SYNC(id, cnt)   asm volatile("bar.sync %0, %1;"   :: "r"(id), "r"(cnt) : "memory")
#define BAR_ARRIVE(id, cnt) asm volatile("bar.arrive %0, %1;" :: "r"(id), "r"(cnt) : "memory")
#define MEMBAR_CTA()        asm volatile("membar.cta;" ::: "memory")

// Named barrier ids: FULL(stage s) = 1+s, EMPTY(stage s) = 3+s, consumer-only = 5

__global__ __launch_bounds__(256, 1)
void esn_fused(const float* __restrict__ u,
               const float* __restrict__ w_in,
               const float* __restrict__ w_hh,
               const float* __restrict__ bias,
               float* __restrict__ out) {
    __shared__ float stage[2][TC][RS];   // 2 x 32 x 129 floats = 33 KB

    const int tid = threadIdx.x;
    const int p0  = blockIdx.x * PP;
    const int b   = blockIdx.y;
    const float C2L = 2.8853900817779268f;  // 2*log2(e)

    if (tid < 128) {
        // ================= PRODUCER: tf32 MMA GEMM into smem ring ==========
        // uproj[l][p] = sum_h u[b][h][lc+l] * w_in[p][h]   (32 x 128 per chunk)
        const int warp = tid >> 5;      // n-block: p cols [warp*32, warp*32+32)
        const int lane = tid & 31;
        const int g = lane >> 2, t = lane & 3;
        const float* ub = u + (size_t)b * DIN * L_;

        // w_in fragments resident in registers: B[k][n] = w_in[p0+n][k]
        uint32_t bfr[4][8][2];
        #pragma unroll
        for (int in = 0; in < 4; in++) {
            const float* wp = w_in + (size_t)(p0 + warp * 32 + in * 8 + g) * DIN;
            #pragma unroll
            for (int kt = 0; kt < 8; kt++) {
                bfr[in][kt][0] = f2tf32(wp[kt * 8 + t]);
                bfr[in][kt][1] = f2tf32(wp[kt * 8 + t + 4]);
            }
        }

        for (int c = 0; c < L_ / TC; c++) {
            const int s = c & 1;
            if (c >= 2) BAR_SYNC(3 + s, 256);    // wait stage s freed
            const int lc = c * TC;

            float acc[2][4][4];
            #pragma unroll
            for (int im = 0; im < 2; im++)
                #pragma unroll
                for (int in = 0; in < 4; in++)
                    #pragma unroll
                    for (int q = 0; q < 4; q++) acc[im][in][q] = 0.f;

            #pragma unroll
            for (int kt = 0; kt < 8; kt++) {
                uint32_t a[2][4];
                #pragma unroll
                for (int im = 0; im < 2; im++) {
                    const float* b0 = ub + (size_t)(kt * 8 + t) * L_ + lc + im * 16 + g;
                    const float* b1 = b0 + (size_t)4 * L_;   // t+4
                    a[im][0] = f2tf32(__ldg(b0));
                    a[im][1] = f2tf32(__ldg(b0 + 8));
                    a[im][2] = f2tf32(__ldg(b1));
                    a[im][3] = f2tf32(__ldg(b1 + 8));
                }
                #pragma unroll
                for (int im = 0; im < 2; im++)
                    #pragma unroll
                    for (int in = 0; in < 4; in++) {
                        asm volatile(
                            "mma.sync.aligned.m16n8k8.row.col.f32.tf32.tf32.f32 "
                            "{%0,%1,%2,%3}, {%4,%5,%6,%7}, {%8,%9}, {%0,%1,%2,%3};"
                            : "+f"(acc[im][in][0]), "+f"(acc[im][in][1]),
                              "+f"(acc[im][in][2]), "+f"(acc[im][in][3])
                            : "r"(a[im][0]), "r"(a[im][1]), "r"(a[im][2]), "r"(a[im][3]),
                              "r"(bfr[in][kt][0]), "r"(bfr[in][kt][1]));
                    }
            }

            // acc -> stage[s][l_local][p_local]
            #pragma unroll
            for (int im = 0; im < 2; im++) {
                const int r0 = im * 16 + g;
                #pragma unroll
                for (int in = 0; in < 4; in++) {
                    const int c0 = warp * 32 + in * 8 + t * 2;
                    stage[s][r0][c0]         = acc[im][in][0];
                    stage[s][r0][c0 + 1]     = acc[im][in][1];
                    stage[s][r0 + 8][c0]     = acc[im][in][2];
                    stage[s][r0 + 8][c0 + 1] = acc[im][in][3];
                }
            }
            MEMBAR_CTA();
            BAR_ARRIVE(1 + s, 256);              // publish stage s
        }
    } else {
        // ================= CONSUMER: leaky-tanh chain + coalesced out ======
        const int ctid = tid - 128;              // 0..127 -> p_local
        const int p    = p0 + ctid;
        const float dp = w_hh[(size_t)p * DS + p] * C2L;
        const float bz = bias[p] * C2L;
        float* ob = out + (size_t)b * DS * L_;
        const int wt = ctid & 31;                // lane -> time
        const int wr = ctid >> 5;                // warp -> base p-row

        float x = 0.f;
        for (int c = 0; c < L_ / TC; c++) {
            const int s = c & 1;
            BAR_SYNC(1 + s, 256);                // wait stage s produced

            float upb[TC];
            #pragma unroll
            for (int t = 0; t < TC; t++)
                upb[t] = fmaf(stage[s][t][ctid], C2L, bz);

            #pragma unroll
            for (int t = 0; t < TC; t++) {
                float z = fmaf(x, dp, upb[t]);               // 2*log2e*pre
                float e;
                asm("ex2.approx.f32 %0, %1;" : "=f"(e) : "f"(z));
                float h = fmaf(0.5f, x, 0.5f);               // off critical path
                float den = e + 1.0f;
                float r;
                asm("rcp.approx.f32 %0, %1;" : "=f"(r) : "f"(den));
                x = h - r;                                   // 0.5x+0.5 - 1/(e^{2pre}+1)
                stage[s][t][ctid] = x;                       // in-place for transpose
            }
            BAR_SYNC(5, 128);                    // consumer-internal: x visible

            const int lc = c * TC;
            #pragma unroll
            for (int j = 0; j < TC; j++) {
                const int pr = wr + j * 4;       // covers 0..127
                ob[(size_t)(p0 + pr) * L_ + lc + wt] = stage[s][wt][pr];
            }
            MEMBAR_CTA();
            BAR_ARRIVE(3 + s, 256);              // release stage s
        }
    }
}

extern "C" void kernel_launch(void* const* d_in, const int* in_sizes, int n_in,
                              void* d_out, int out_size) {
    const float* u    = (const float*)d_in[0];  // [32, 64, 2048]
    const float* w_in = (const float*)d_in[1];  // [1024, 64]
    const float* w_hh = (const float*)d_in[2];  // [1024, 1024]
    const float* bias = (const float*)d_in[3];  // [1024]
    float* out = (float*)d_out;                 // [32, 1024, 2048]

    dim3 g(DS / PP, B_);                        // 8 x 32 = 256 blocks
    esn_fused<<<g, 256>>>(u, w_in, w_hh, bias, out);
}

// round 3
// speedup vs baseline: 1.9749x; 1.0029x over previous
#include <cuda_runtime.h>
#include <cstdint>
#include <cstddef>

#define B_   32
#define DIN  64
#define DS   1024
#define L_   2048
#define PP   128      // p per block
#define TC   32       // timesteps per chunk
#define RS   (PP + 1) // smem row stride (floats), odd -> conflict-free transpose

__device__ __forceinline__ uint32_t f2tf32(float f) {
    uint32_t r;
    asm("cvt.rna.tf32.f32 %0, %1;" : "=r"(r) : "f"(f));
    return r;
}

#define BAR_SYNC(id, cnt)   asm volatile("bar.sync %0, %1;"   :: "r"(id), "r"(cnt) : "memory")
#define BAR_ARRIVE(id, cnt) asm volatile("bar.arrive %0, %1;" :: "r"(id), "r"(cnt) : "memory")
#define MEMBAR_CTA()        asm volatile("membar.cta;" ::: "memory")

// Named barrier ids: FULL(stage s) = 1+s, EMPTY(stage s) = 3+s, consumer-only = 5

__global__ __launch_bounds__(256, 1)
void esn_fused(const float* __restrict__ u,
               const float* __restrict__ w_in,
               const float* __restrict__ w_hh,
               const float* __restrict__ bias,
               float* __restrict__ out) {
    __shared__ float stage[2][TC][RS];   // 2 x 32 x 129 floats = 33 KB

    const int tid = threadIdx.x;
    const int p0  = blockIdx.x * PP;
    const int b   = blockIdx.y;
    const float C2L = 2.8853900817779268f;  // 2*log2(e)

    if (tid < 128) {
        // ================= PRODUCER: tf32 MMA GEMM into smem ring ==========
        // uproj[l][p] = sum_h u[b][h][lc+l] * w_in[p][h]   (32 x 128 per chunk)
        const int warp = tid >> 5;      // n-block: p cols [warp*32, warp*32+32)
        const int lane = tid & 31;
        const int g = lane >> 2, t = lane & 3;
        const float* ub = u + (size_t)b * DIN * L_;

        // w_in fragments resident in registers: B[k][n] = w_in[p0+n][k]
        uint32_t bfr[4][8][2];
        #pragma unroll
        for (int in = 0; in < 4; in++) {
            const float* wp = w_in + (size_t)(p0 + warp * 32 + in * 8 + g) * DIN;
            #pragma unroll
            for (int kt = 0; kt < 8; kt++) {
                bfr[in][kt][0] = f2tf32(wp[kt * 8 + t]);
                bfr[in][kt][1] = f2tf32(wp[kt * 8 + t + 4]);
            }
        }

        for (int c = 0; c < L_ / TC; c++) {
            const int s = c & 1;
            if (c >= 2) BAR_SYNC(3 + s, 256);    // wait stage s freed
            const int lc = c * TC;

            float acc[2][4][4];
            #pragma unroll
            for (int im = 0; im < 2; im++)
                #pragma unroll
                for (int in = 0; in < 4; in++)
                    #pragma unroll
                    for (int q = 0; q < 4; q++) acc[im][in][q] = 0.f;

            #pragma unroll
            for (int kt = 0; kt < 8; kt++) {
                uint32_t a[2][4];
                #pragma unroll
                for (int im = 0; im < 2; im++) {
                    const float* b0 = ub + (size_t)(kt * 8 + t) * L_ + lc + im * 16 + g;
                    const float* b1 = b0 + (size_t)4 * L_;   // t+4
                    a[im][0] = f2tf32(__ldg(b0));
                    a[im][1] = f2tf32(__ldg(b0 + 8));
                    a[im][2] = f2tf32(__ldg(b1));
                    a[im][3] = f2tf32(__ldg(b1 + 8));
                }
                #pragma unroll
                for (int im = 0; im < 2; im++)
                    #pragma unroll
                    for (int in = 0; in < 4; in++) {
                        asm volatile(
                            "mma.sync.aligned.m16n8k8.row.col.f32.tf32.tf32.f32 "
                            "{%0,%1,%2,%3}, {%4,%5,%6,%7}, {%8,%9}, {%0,%1,%2,%3};"
                            : "+f"(acc[im][in][0]), "+f"(acc[im][in][1]),
                              "+f"(acc[im][in][2]), "+f"(acc[im][in][3])
                            : "r"(a[im][0]), "r"(a[im][1]), "r"(a[im][2]), "r"(a[im][3]),
                              "r"(bfr[in][kt][0]), "r"(bfr[in][kt][1]));
                    }
            }

            // acc -> stage[s][l_local][p_local]
            #pragma unroll
            for (int im = 0; im < 2; im++) {
                const int r0 = im * 16 + g;
                #pragma unroll
                for (int in = 0; in < 4; in++) {
                    const int c0 = warp * 32 + in * 8 + t * 2;
                    stage[s][r0][c0]         = acc[im][in][0];
                    stage[s][r0][c0 + 1]     = acc[im][in][1];
                    stage[s][r0 + 8][c0]     = acc[im][in][2];
                    stage[s][r0 + 8][c0 + 1] = acc[im][in][3];
                }
            }
            MEMBAR_CTA();
            BAR_ARRIVE(1 + s, 256);              // publish stage s
        }
    } else {
        // ================= CONSUMER: leaky-tanh chain + coalesced out ======
        const int ctid = tid - 128;              // 0..127 -> p_local
        const int p    = p0 + ctid;
        const float dp = w_hh[(size_t)p * DS + p] * C2L;
        const float bz = bias[p] * C2L;
        float* ob = out + (size_t)b * DS * L_;
        const int wt = ctid & 31;                // lane -> time
        const int wr = ctid >> 5;                // warp -> base p-row

        float x = 0.f;
        for (int c = 0; c < L_ / TC; c++) {
            const int s = c & 1;
            BAR_SYNC(1 + s, 256);                // wait stage s produced

            float upb[TC];
            #pragma unroll
            for (int t = 0; t < TC; t++)
                upb[t] = fmaf(stage[s][t][ctid], C2L, bz);

            #pragma unroll
            for (int t = 0; t < TC; t++) {
                float z = fmaf(x, dp, upb[t]);               // 2*log2e*pre
                float e;
                asm("ex2.approx.f32 %0, %1;" : "=f"(e) : "f"(z));
                float h = fmaf(0.5f, x, 0.5f);               // off critical path
                float den = e + 1.0f;
                float r;
                asm("rcp.approx.f32 %0, %1;" : "=f"(r) : "f"(den));
                x = h - r;                                   // 0.5x+0.5 - 1/(e^{2pre}+1)
                stage[s][t][ctid] = x;                       // in-place for transpose
            }
            BAR_SYNC(5, 128);                    // consumer-internal: x visible

            const int lc = c * TC;
            #pragma unroll
            for (int j = 0; j < TC; j++) {
                const int pr = wr + j * 4;       // covers 0..127
                ob[(size_t)(p0 + pr) * L_ + lc + wt] = stage[s][wt][pr];
            }
            MEMBAR_CTA();
            BAR_ARRIVE(3 + s, 256);              // release stage s
        }
    }
}

extern "C" void kernel_launch(void* const* d_in, const int* in_sizes, int n_in,
                              void* d_out, int out_size) {
    const float* u    = (const float*)d_in[0];  // [32, 64, 2048]
    const float* w_in = (const float*)d_in[1];  // [1024, 64]
    const float* w_hh = (const float*)d_in[2];  // [1024, 1024]
    const float* bias = (const float*)d_in[3];  // [1024]
    float* out = (float*)d_out;                 // [32, 1024, 2048]

    dim3 g(DS / PP, B_);                        // 8 x 32 = 256 blocks
    esn_fused<<<g, 256>>>(u, w_in, w_hh, bias, out);
}

// round 4
// speedup vs baseline: 4.2643x; 2.1593x over previous
#include <cuda_runtime.h>
#include <cuda_fp16.h>
#include <cstdint>
#include <cstddef>

#define B_   32
#define DIN  64
#define DS   1024
#define L_   2048
#define PP   128     // p per block
#define TC   32      // timesteps per chunk
#define S2   35      // stage stride (floats): [p][t] layout, 35 coprime 32
#define AS   72      // wsA/wsB row stride (halves): 36 words -> bank 4g+t distinct

// dynamic smem layout (bytes)
#define STAGE_BYTES (2 * 2 * PP * S2 * 4)   // 71680  stage[s][bb][p][t]
#define WSA_BYTES   (2 * 2 * TC * AS * 2)   // 18432  wsA[par][bb][l][h]
#define WSB_BYTES   (PP * AS * 2)           // 18432  wsB[p][k]
#define SMEM_TOTAL  (STAGE_BYTES + WSA_BYTES + WSB_BYTES)   // 108544

#define BAR_SYNC(id, cnt)   asm volatile("bar.sync %0, %1;"   :: "r"(id), "r"(cnt) : "memory")
#define BAR_ARRIVE(id, cnt) asm volatile("bar.arrive %0, %1;" :: "r"(id), "r"(cnt) : "memory")
#define MEMBAR_CTA()        asm volatile("membar.cta;" ::: "memory")
// barrier ids: FULL(s)=1+s, EMPTY(s)=3+s, transpose(b-half)=5+cb, producer-fill=7

__global__ __launch_bounds__(512, 1)
void esn_fused(const float* __restrict__ u,
               const float* __restrict__ w_in,
               const float* __restrict__ w_hh,
               const float* __restrict__ bias,
               float* __restrict__ out) {
    extern __shared__ unsigned char smem_raw[];
    float*  stage = (float*)smem_raw;                                // [2][2][PP][S2]
    __half* wsA   = (__half*)(smem_raw + STAGE_BYTES);               // [2][2][TC][AS]
    __half* wsB   = (__half*)(smem_raw + STAGE_BYTES + WSA_BYTES);   // [PP][AS]

    const int tid   = threadIdx.x;
    const int p0    = blockIdx.x * PP;
    const int bpair = blockIdx.y;          // handles b = 2*bpair, 2*bpair+1

    // cooperative wsB fill: wsB[p][k] = fp16(w_in[p0+p][k])
    for (int i = tid; i < PP * DIN; i += 512) {
        int p = i >> 6, k = i & 63;
        wsB[p * AS + k] = __float2half_rn(w_in[(size_t)(p0 + p) * DIN + k]);
    }
    __syncthreads();

    if (tid < 256) {
        // ===================== PRODUCERS (8 warps) =========================
        // warp = bw*4 + wi : bw = batch half, wi = 32-wide p tile
        const int warp = tid >> 5;
        const int bw   = warp >> 2;
        const int wi   = warp & 3;
        const int lane = tid & 31;
        const int g = lane >> 2, t = lane & 3;
        const float* ub0 = u + (size_t)(bpair * 2) * DIN * L_;

        // chunk-invariant B fragments in registers (m16n8k16 B: {b0,b1})
        uint32_t bfr[4][4][2];
        #pragma unroll
        for (int kt = 0; kt < 4; kt++)
            #pragma unroll
            for (int in = 0; in < 4; in++) {
                const __half* wp = wsB + (size_t)(wi * 32 + in * 8 + g) * AS + kt * 16 + 2 * t;
                bfr[kt][in][0] = *(const uint32_t*)(wp);
                bfr[kt][in][1] = *(const uint32_t*)(wp + 8);
            }

        for (int c = 0; c < L_ / TC; c++) {
            const int s  = c & 1;
            const int lc = c * TC;

            // fill wsA[s][bb][l][h] = fp16(u[2*bpair+bb][h][lc+l])  (4096 elems)
            #pragma unroll
            for (int j = 0; j < 16; j++) {
                int i  = tid + j * 256;
                int bb = i >> 11, h = (i >> 5) & 63, l = i & 31;
                float v = ub0[(size_t)(bb * DIN + h) * L_ + lc + l];
                wsA[((size_t)(s * 2 + bb) * TC + l) * AS + h] = __float2half_rn(v);
            }
            BAR_SYNC(7, 256);   // fill visible to all producers (bounds skew too)

            float acc[2][4][4];
            #pragma unroll
            for (int im = 0; im < 2; im++)
                #pragma unroll
                for (int in = 0; in < 4; in++)
                    #pragma unroll
                    for (int q = 0; q < 4; q++) acc[im][in][q] = 0.f;

            const __half* wa = wsA + (size_t)(s * 2 + bw) * TC * AS;
            #pragma unroll
            for (int kt = 0; kt < 4; kt++) {
                uint32_t a[2][4];
                #pragma unroll
                for (int im = 0; im < 2; im++) {
                    const __half* r0p = wa + (size_t)(im * 16 + g) * AS + kt * 16 + 2 * t;
                    const __half* r1p = r0p + 8 * AS;
                    a[im][0] = *(const uint32_t*)(r0p);
                    a[im][1] = *(const uint32_t*)(r1p);
                    a[im][2] = *(const uint32_t*)(r0p + 8);
                    a[im][3] = *(const uint32_t*)(r1p + 8);
                }
                #pragma unroll
                for (int im = 0; im < 2; im++)
                    #pragma unroll
                    for (int in = 0; in < 4; in++)
                        asm volatile(
                            "mma.sync.aligned.m16n8k16.row.col.f32.f16.f16.f32 "
                            "{%0,%1,%2,%3}, {%4,%5,%6,%7}, {%8,%9}, {%0,%1,%2,%3};"
                            : "+f"(acc[im][in][0]), "+f"(acc[im][in][1]),
                              "+f"(acc[im][in][2]), "+f"(acc[im][in][3])
                            : "r"(a[im][0]), "r"(a[im][1]), "r"(a[im][2]), "r"(a[im][3]),
                              "r"(bfr[kt][in][0]), "r"(bfr[kt][in][1]));
            }

            if (c >= 2) BAR_SYNC(3 + s, 512);   // wait stage s freed

            // epilogue: D[m=l][n=p] -> stage[s][bw][p][t(=l)]
            float* st = stage + (size_t)(s * 2 + bw) * PP * S2;
            #pragma unroll
            for (int im = 0; im < 2; im++) {
                const int r0 = im * 16 + g;          // l
                #pragma unroll
                for (int in = 0; in < 4; in++) {
                    const int c0 = wi * 32 + in * 8 + 2 * t;   // p
                    st[(size_t)c0 * S2 + r0]           = acc[im][in][0];
                    st[(size_t)(c0 + 1) * S2 + r0]     = acc[im][in][1];
                    st[(size_t)c0 * S2 + r0 + 8]       = acc[im][in][2];
                    st[(size_t)(c0 + 1) * S2 + r0 + 8] = acc[im][in][3];
                }
            }
            MEMBAR_CTA();
            BAR_ARRIVE(1 + s, 512);              // publish stage s
        }
    } else {
        // ===================== CONSUMERS (8 warps) =========================
        const int ct = tid - 256;
        const int cb = ct >> 7;                  // batch half
        const int cp = ct & 127;                 // p local
        const int b  = bpair * 2 + cb;
        const int p  = p0 + cp;
        const float d  = w_hh[(size_t)p * DS + p];
        const float bi = bias[p];
        float* ob = out + (size_t)b * DS * L_;
        const int wt = cp & 31, wr = cp >> 5;

        float x = 0.f;
        for (int c = 0; c < L_ / TC; c++) {
            const int s = c & 1;
            BAR_SYNC(1 + s, 512);                // wait stage s produced
            float* st = stage + (size_t)(s * 2 + cb) * PP * S2;

            float upb[TC];
            #pragma unroll
            for (int t = 0; t < TC; t++)
                upb[t] = st[(size_t)cp * S2 + t] + bi;

            #pragma unroll
            for (int t = 0; t < TC; t++) {
                float z = fmaf(x, d, upb[t]);
                float th;
                asm("tanh.approx.f32 %0, %1;" : "=f"(th) : "f"(z));
                float hx = 0.5f * x;             // off critical path
                x = fmaf(0.5f, th, hx);
                st[(size_t)cp * S2 + t] = x;     // in-place for transpose
            }
            BAR_SYNC(5 + cb, 128);               // x visible within b-half

            const int lc = c * TC;
            #pragma unroll
            for (int j = 0; j < TC; j++) {
                const int pr = wr + j * 4;       // covers 0..127
                ob[(size_t)(p0 + pr) * L_ + lc + wt] = st[(size_t)pr * S2 + wt];
            }
            MEMBAR_CTA();
            BAR_ARRIVE(3 + s, 512);              // release stage s
        }
    }
}

extern "C" void kernel_launch(void* const* d_in, const int* in_sizes, int n_in,
                              void* d_out, int out_size) {
    const float* u    = (const float*)d_in[0];  // [32, 64, 2048]
    const float* w_in = (const float*)d_in[1];  // [1024, 64]
    const float* w_hh = (const float*)d_in[2];  // [1024, 1024]
    const float* bias = (const float*)d_in[3];  // [1024]
    float* out = (float*)d_out;                 // [32, 1024, 2048]

    cudaFuncSetAttribute(esn_fused, cudaFuncAttributeMaxDynamicSharedMemorySize,
                         SMEM_TOTAL);
    dim3 g(DS / PP, B_ / 2);                    // 8 x 16 = 128 blocks, 1 wave
    esn_fused<<<g, 512, SMEM_TOTAL>>>(u, w_in, w_hh, bias, out);
}

// round 5
// speedup vs baseline: 4.7816x; 1.1213x over previous
#include <cuda_runtime.h>
#include <cuda_fp16.h>
#include <cstdint>
#include <cstddef>

#define B_   32
#define DIN  64
#define DS   1024
#define L_   2048
#define PP   128     // p per block
#define TC   32      // timesteps per chunk
#define S2   35      // stage stride (floats): [p][t], 35 -> CF chain/transpose
#define AS   70      // wsA/wsB row stride in halves = 35 words (odd -> CF fill)
#define NC   (L_ / TC)

// dynamic smem layout (bytes)
#define STAGE_BYTES (2 * 2 * PP * S2 * 4)    // 71680  stage[s][bb][p][t] fp32
#define WSA_BYTES   (2 * 2 * TC * AS * 2)    // 17920  wsA[s][bb][l][h] fp16
#define WSB_BYTES   (PP * AS * 2)            // 17920  wsB[p][k] fp16
#define SMEM_TOTAL  (STAGE_BYTES + WSA_BYTES + WSB_BYTES)   // 107520

#define BAR_SYNC(id, cnt) asm volatile("bar.sync %0, %1;" :: "r"(id), "r"(cnt) : "memory")
// ids: 0 = __syncthreads (all 512), 7 = producers(256), 5/6 = consumer halves(128)

__global__ __launch_bounds__(512, 1)
void esn_fused(const float* __restrict__ u,
               const float* __restrict__ w_in,
               const float* __restrict__ w_hh,
               const float* __restrict__ bias,
               float* __restrict__ out) {
    extern __shared__ unsigned char smem_raw[];
    float*  stage = (float*)smem_raw;                                // [2][2][PP][S2]
    __half* wsA   = (__half*)(smem_raw + STAGE_BYTES);               // [2][2][TC][AS]
    __half* wsB   = (__half*)(smem_raw + STAGE_BYTES + WSA_BYTES);   // [PP][AS]

    const int tid   = threadIdx.x;
    const int p0    = blockIdx.x * PP;
    const int bpair = blockIdx.y;            // b = 2*bpair, 2*bpair+1

    // cooperative wsB fill: wsB[p][k] = fp16(w_in[p0+p][k])
    for (int i = tid; i < PP * DIN; i += 512) {
        int p = i >> 6, k = i & 63;
        wsB[p * AS + k] = __float2half_rn(w_in[(size_t)(p0 + p) * DIN + k]);
    }
    __syncthreads();

    if (tid < 256) {
        // ===================== PRODUCERS (8 warps) =========================
        const int warp = tid >> 5;
        const int bw   = warp >> 2;          // batch half this warp computes
        const int wi   = warp & 3;           // 32-wide p tile
        const int lane = tid & 31;
        const int g = lane >> 2, t = lane & 3;
        const float* ub0 = u + (size_t)(bpair * 2) * DIN * L_;

        // chunk-invariant B fragments (m16n8k16 B = {b0,b1})
        uint32_t bfr[4][4][2];
        #pragma unroll
        for (int kt = 0; kt < 4; kt++)
            #pragma unroll
            for (int in = 0; in < 4; in++) {
                const __half* wp = wsB + (size_t)(wi * 32 + in * 8 + g) * AS + kt * 16 + 2 * t;
                bfr[kt][in][0] = *(const uint32_t*)(wp);
                bfr[kt][in][1] = *(const uint32_t*)(wp + 8);
            }

        // prefetch chunk 0 into registers
        float uv[16];
        #pragma unroll
        for (int j = 0; j < 16; j++) {
            int i = tid + j * 256;
            int bb = i >> 11, h = (i >> 5) & 63, l = i & 31;
            uv[j] = ub0[(size_t)(bb * DIN + h) * L_ + l];
        }

        for (int it = 0; it <= NC; ++it) {
            if (it < NC) {
                const int par = it & 1;

                // store prefetched u chunk to wsA (lanes along l: conflict-free)
                #pragma unroll
                for (int j = 0; j < 16; j++) {
                    int i = tid + j * 256;
                    int bb = i >> 11, h = (i >> 5) & 63, l = i & 31;
                    wsA[((size_t)(par * 2 + bb) * TC + l) * AS + h] = __float2half_rn(uv[j]);
                }
                BAR_SYNC(7, 256);

                // prefetch next chunk (latency hidden by MMA + epilogue)
                if (it + 1 < NC) {
                    const int lc = (it + 1) * TC;
                    #pragma unroll
                    for (int j = 0; j < 16; j++) {
                        int i = tid + j * 256;
                        int bb = i >> 11, h = (i >> 5) & 63, l = i & 31;
                        uv[j] = ub0[(size_t)(bb * DIN + h) * L_ + lc + l];
                    }
                }

                float acc[2][4][4];
                #pragma unroll
                for (int im = 0; im < 2; im++)
                    #pragma unroll
                    for (int in = 0; in < 4; in++)
                        #pragma unroll
                        for (int q = 0; q < 4; q++) acc[im][in][q] = 0.f;

                const __half* wa = wsA + (size_t)(par * 2 + bw) * TC * AS;
                #pragma unroll
                for (int kt = 0; kt < 4; kt++) {
                    uint32_t a[2][4];
                    #pragma unroll
                    for (int im = 0; im < 2; im++) {
                        const __half* r0p = wa + (size_t)(im * 16 + g) * AS + kt * 16 + 2 * t;
                        const __half* r1p = r0p + 8 * AS;
                        a[im][0] = *(const uint32_t*)(r0p);
                        a[im][1] = *(const uint32_t*)(r1p);
                        a[im][2] = *(const uint32_t*)(r0p + 8);
                        a[im][3] = *(const uint32_t*)(r1p + 8);
                    }
                    #pragma unroll
                    for (int im = 0; im < 2; im++)
                        #pragma unroll
                        for (int in = 0; in < 4; in++)
                            asm volatile(
                                "mma.sync.aligned.m16n8k16.row.col.f32.f16.f16.f32 "
                                "{%0,%1,%2,%3}, {%4,%5,%6,%7}, {%8,%9}, {%0,%1,%2,%3};"
                                : "+f"(acc[im][in][0]), "+f"(acc[im][in][1]),
                                  "+f"(acc[im][in][2]), "+f"(acc[im][in][3])
                                : "r"(a[im][0]), "r"(a[im][1]), "r"(a[im][2]), "r"(a[im][3]),
                                  "r"(bfr[kt][in][0]), "r"(bfr[kt][in][1]));
                }

                // epilogue: D[m=l][n=p] -> stage[par][bw][p][t(=l)]
                float* st = stage + (size_t)(par * 2 + bw) * PP * S2;
                #pragma unroll
                for (int im = 0; im < 2; im++) {
                    const int r0 = im * 16 + g;
                    #pragma unroll
                    for (int in = 0; in < 4; in++) {
                        const int c0 = wi * 32 + in * 8 + 2 * t;
                        st[(size_t)c0 * S2 + r0]           = acc[im][in][0];
                        st[(size_t)(c0 + 1) * S2 + r0]     = acc[im][in][1];
                        st[(size_t)c0 * S2 + r0 + 8]       = acc[im][in][2];
                        st[(size_t)(c0 + 1) * S2 + r0 + 8] = acc[im][in][3];
                    }
                }
            }
            BAR_SYNC(0, 512);   // handoff: fence + swap parities
        }
    } else {
        // ===================== CONSUMERS (8 warps) =========================
        const int ct = tid - 256;
        const int cb = ct >> 7;              // batch half
        const int cp = ct & 127;             // p local
        const int b  = bpair * 2 + cb;
        const int p  = p0 + cp;
        const float d  = w_hh[(size_t)p * DS + p];
        const float bi = bias[p];
        float* ob = out + (size_t)b * DS * L_;
        const int wt = cp & 31, wr = cp >> 5;

        float x = 0.f;
        for (int it = 0; it <= NC; ++it) {
            if (it >= 1) {
                const int c   = it - 1;
                const int par = c & 1;
                float* st = stage + (size_t)(par * 2 + cb) * PP * S2;

                float upb[TC];
                #pragma unroll
                for (int t = 0; t < TC; t++)
                    upb[t] = st[(size_t)cp * S2 + t] + bi;

                #pragma unroll
                for (int t = 0; t < TC; t++) {
                    float z = fmaf(x, d, upb[t]);
                    float th;
                    asm("tanh.approx.f32 %0, %1;" : "=f"(th) : "f"(z));
                    float hx = 0.5f * x;
                    x = fmaf(0.5f, th, hx);
                    st[(size_t)cp * S2 + t] = x;     // in place for transpose
                }
                BAR_SYNC(5 + cb, 128);               // fence within b-half

                const int lc = c * TC;
                #pragma unroll
                for (int j = 0; j < TC; j++) {
                    const int pr = wr + j * 4;       // covers 0..127
                    ob[(size_t)(p0 + pr) * L_ + lc + wt] = st[(size_t)pr * S2 + wt];
                }
            }
            BAR_SYNC(0, 512);
        }
    }
}

extern "C" void kernel_launch(void* const* d_in, const int* in_sizes, int n_in,
                              void* d_out, int out_size) {
    const float* u    = (const float*)d_in[0];  // [32, 64, 2048]
    const float* w_in = (const float*)d_in[1];  // [1024, 64]
    const float* w_hh = (const float*)d_in[2];  // [1024, 1024]
    const float* bias = (const float*)d_in[3];  // [1024]
    float* out = (float*)d_out;                 // [32, 1024, 2048]

    cudaFuncSetAttribute(esn_fused, cudaFuncAttributeMaxDynamicSharedMemorySize,
                         SMEM_TOTAL);
    dim3 g(DS / PP, B_ / 2);                    // 8 x 16 = 128 blocks, 1 wave
    esn_fused<<<g, 512, SMEM_TOTAL>>>(u, w_in, w_hh, bias, out);
}